// round 7
// baseline (speedup 1.0000x reference)
#include <cuda_runtime.h>
#include <cstdint>

// ---------------------------------------------------------------------------
// Problem constants
// ---------------------------------------------------------------------------
#define B_    256
#define T_    512
#define S_    256
#define L_    36
#define DIN_  8
#define OUT_  10
#define W_    256
#define NBLK  128   // persistent grid size (<= 148 SMs -> single wave, co-resident)

// ---------------------------------------------------------------------------
// Device scratch (allocation-free: __device__ globals)
// ---------------------------------------------------------------------------
__device__ float    g_h[B_ * S_];                     // current hidden state [B,S]
__device__ float    g_z2[B_ * W_];                    // z2 buffer [B,W]
__device__ float    g_hidden[(T_ + 1) * B_ * S_];     // history [t][b][s] (~134 MB)
__device__ unsigned g_bar;                            // grid barrier counter

// ---------------------------------------------------------------------------
// Math helpers
// ---------------------------------------------------------------------------
__device__ __forceinline__ float softplus_f(float x) {
    return (x > 0.f) ? (x + log1pf(__expf(-x))) : log1pf(__expf(x));
}
__device__ __forceinline__ float tanh_f(float x) {
    float e = __expf(2.f * x);
    return 1.f - __fdividef(2.f, e + 1.f);
}

// ---------------------------------------------------------------------------
// Software grid barrier. Requires all NBLK blocks co-resident (true: one wave).
// Monotonic counter; reset to 0 by init_kernel each replay.
// ---------------------------------------------------------------------------
__device__ __forceinline__ void grid_barrier(unsigned target) {
    __syncthreads();
    if (threadIdx.x == 0) {
        __threadfence();
        atomicAdd(&g_bar, 1u);
        while (*((volatile unsigned*)&g_bar) < target) { __nanosleep(64); }
        __threadfence();
    }
    __syncthreads();
}

// ---------------------------------------------------------------------------
// Generic 4-row x (256 -> 256) dense layer (NT dot, W row-major [out][in]).
// Block: 256 threads, 4 batch rows.  wtile: smem [256][36] staging.
// ---------------------------------------------------------------------------
__device__ __forceinline__ void layer256(const float* __restrict__ in_s,
                                         float* __restrict__ out_s,
                                         const float* __restrict__ W,
                                         const float* __restrict__ bias,
                                         float* __restrict__ wtile,
                                         int tid, bool do_softplus)
{
    const int lane = tid & 31;
    const int warp = tid >> 5;
    const int r    = warp >> 1;
    const int half = warp & 1;
    int col[4];
#pragma unroll
    for (int j = 0; j < 4; ++j) col[j] = lane + 32 * half + 64 * j;

    float acc[4] = {0.f, 0.f, 0.f, 0.f};

    for (int kc = 0; kc < 8; ++kc) {
        __syncthreads();
#pragma unroll
        for (int u = 0; u < 8; ++u) {
            int e  = tid + 256 * u;
            int w  = e >> 3;
            int k4 = (e & 7) << 2;
            float4 v = *reinterpret_cast<const float4*>(W + w * 256 + kc * 32 + k4);
            *reinterpret_cast<float4*>(wtile + w * 36 + k4) = v;
        }
        __syncthreads();
#pragma unroll
        for (int kg = 0; kg < 8; ++kg) {
            float4 a = *reinterpret_cast<const float4*>(in_s + r * 256 + kc * 32 + kg * 4);
#pragma unroll
            for (int j = 0; j < 4; ++j) {
                float4 b = *reinterpret_cast<const float4*>(wtile + col[j] * 36 + kg * 4);
                acc[j] = fmaf(a.x, b.x, acc[j]);
                acc[j] = fmaf(a.y, b.y, acc[j]);
                acc[j] = fmaf(a.z, b.z, acc[j]);
                acc[j] = fmaf(a.w, b.w, acc[j]);
            }
        }
    }
    __syncthreads();
#pragma unroll
    for (int j = 0; j < 4; ++j) {
        float v = acc[j] + __ldg(bias + col[j]);
        if (do_softplus) v = softplus_f(v);
        out_s[r * 256 + col[j]] = v;
    }
}

// ---------------------------------------------------------------------------
// Init kernel: h0 = initMLP(x0) -> g_h, g_hidden[0]; also resets g_bar.
// grid = 64 x 256.
// ---------------------------------------------------------------------------
__global__ void __launch_bounds__(256)
init_kernel(const float* __restrict__ x0,
            const float* __restrict__ iW1, const float* __restrict__ ib1,
            const float* __restrict__ iW2, const float* __restrict__ ib2,
            const float* __restrict__ iW3, const float* __restrict__ ib3)
{
    __shared__ __align__(16) float wtile[256 * 36];
    __shared__ __align__(16) float buf0[4 * 256];
    __shared__ __align__(16) float buf1[4 * 256];
    __shared__ float sx0[4 * 8];

    const int tid  = threadIdx.x;
    const int row0 = blockIdx.x * 4;

    if (blockIdx.x == 0 && tid == 0) g_bar = 0u;

    if (tid < 32) sx0[tid] = x0[row0 * DIN_ + tid];
#pragma unroll
    for (int u = 0; u < 8; ++u) wtile[tid + 256 * u] = iW1[tid + 256 * u];
    __syncthreads();

    {
        const int lane = tid & 31, warp = tid >> 5;
        const int r = warp >> 1, half = warp & 1;
#pragma unroll
        for (int j = 0; j < 4; ++j) {
            int c = lane + 32 * half + 64 * j;
            float acc = 0.f;
#pragma unroll
            for (int k = 0; k < 8; ++k)
                acc = fmaf(sx0[r * 8 + k], wtile[c * 8 + k], acc);
            buf0[r * 256 + c] = softplus_f(acc + __ldg(ib1 + c));
        }
    }
    layer256(buf0, buf1, iW2, ib2, wtile, tid, true);
    layer256(buf1, buf0, iW3, ib3, wtile, tid, false);
    __syncthreads();
#pragma unroll
    for (int u = 0; u < 4; ++u) {
        int e = tid + 256 * u;
        float v = buf0[e];
        g_h[row0 * 256 + e] = v;
        g_hidden[row0 * 256 + e] = v;
    }
}

// ---------------------------------------------------------------------------
// Persistent step kernel: loops t = 0..T-1 internally with grid barriers.
// grid = 128 blocks x 256 threads (one wave, co-resident).
//
// Phase Z (blocks 0..63): z2 = sp(sp(h W1^T + b1) W2^T + b2), 4 rows/block.
// Phase M (all 128 blocks): m = tanh(z2 W3^T + b3); h += einsum(m, ls);
//   block tile 128 rows x 144 cols; thread tile 8x9.
// ---------------------------------------------------------------------------
__global__ void __launch_bounds__(256, 1)
step_kernel(const float* __restrict__ vW1, const float* __restrict__ vb1,
            const float* __restrict__ vW2, const float* __restrict__ vb2,
            const float* __restrict__ vW3, const float* __restrict__ vb3,
            const float* __restrict__ logsigs)
{
    // shared pool: Z phase needs 9216+1024+1024 = 11264 floats (45 KB)
    //              M phase needs 2112 (As) + 3072 (Bs) + 4608 (lss) + 144 (bsh)
    __shared__ __align__(16) float pool[11264];

    const int tid = threadIdx.x;
    const int bid = blockIdx.x;

    // --- Z-phase carve ---
    float* wtile = pool;              // 9216
    float* buf0  = pool + 9216;       // 1024
    float* buf1  = pool + 10240;      // 1024

    // --- M-phase carve ---
    float* As  = pool;                // [16][132]  = 2112
    float* Bs  = pool + 2112;         // [16][192]  = 3072 (16 col-groups of 12, 9 used)
    float* lss = pool + 5184;         // [128][36]  = 4608
    float* bsh = pool + 9792;         // 144

    // M-phase geometry (constant per block)
    const int tx    = tid & 15;
    const int ty    = tid >> 4;
    const int row0m = (bid & 1) * 128;
    const int n0    = (bid >> 1) * 144;
    const int s0    = (bid >> 1) * 4;
    const int arow  = tid >> 2;            // 0..63
    const int ak4   = (tid & 3) << 2;      // 0,4,8,12
    // B-load slots (fixed across k-tiles): idx = tid + 256*u, u = 0..2 (576 f4)
    int  b_c[3], b_k4[3], b_slot[3];
    bool b_act[3];
#pragma unroll
    for (int u = 0; u < 3; ++u) {
        int idx  = tid + 256 * u;
        b_act[u] = (idx < 576);
        int c    = (idx >> 2) % 144;
        b_c[u]   = c;
        b_k4[u]  = (idx & 3) << 2;
        b_slot[u] = (c / 9) * 12 + (c % 9);
    }
    const int tx12 = tx * 12;
    const int ty8  = ty * 8;
    const int lbase  = (tx & 3) * 9;
    const bool owner = ((tx & 3) == 0);
    const int s_glob = s0 + (tx >> 2);

    unsigned tgt = 0u;

    for (int t = 0; t < T_; ++t) {
        // =================== Phase Z (blocks 0..63) =======================
        if (bid < 64) {
            const int row0 = bid * 4;
#pragma unroll
            for (int u = 0; u < 4; ++u) {
                int e = tid + 256 * u;
                buf0[e] = g_h[row0 * 256 + e];
            }
            layer256(buf0, buf1, vW1, vb1, wtile, tid, true);
            layer256(buf1, buf0, vW2, vb2, wtile, tid, true);
            __syncthreads();
#pragma unroll
            for (int u = 0; u < 4; ++u) {
                int e = tid + 256 * u;
                g_z2[row0 * 256 + e] = buf0[e];
            }
        }
        tgt += NBLK; grid_barrier(tgt);

        // =================== Phase M (all blocks) =========================
        // stage ls[b,l] and bias (regions disjoint from As/Bs)
        for (int idx = tid; idx < 128 * 36; idx += 256) {
            int rb = idx / 36;
            int l  = idx - rb * 36;
            lss[idx] = logsigs[((size_t)(row0m + rb) * T_ + t) * L_ + l];
        }
        if (tid < 144) bsh[tid] = __ldg(vb3 + n0 + tid);

        float acc[8][9];
#pragma unroll
        for (int i = 0; i < 8; ++i)
#pragma unroll
            for (int j = 0; j < 9; ++j) acc[i][j] = 0.f;

        // prefetch k-tile 0
        float4 pa0, pa1, pb[3];
        pa0 = *reinterpret_cast<const float4*>(&g_z2[(row0m + arow) * 256 + ak4]);
        pa1 = *reinterpret_cast<const float4*>(&g_z2[(row0m + arow + 64) * 256 + ak4]);
#pragma unroll
        for (int u = 0; u < 3; ++u)
            if (b_act[u])
                pb[u] = *reinterpret_cast<const float4*>(
                    &vW3[(size_t)(n0 + b_c[u]) * 256 + b_k4[u]]);

        for (int kt = 0; kt < 16; ++kt) {
            __syncthreads();   // previous compute done reading As/Bs
            // store prefetched tile
            As[(ak4 + 0) * 132 + arow] = pa0.x;
            As[(ak4 + 1) * 132 + arow] = pa0.y;
            As[(ak4 + 2) * 132 + arow] = pa0.z;
            As[(ak4 + 3) * 132 + arow] = pa0.w;
            As[(ak4 + 0) * 132 + arow + 64] = pa1.x;
            As[(ak4 + 1) * 132 + arow + 64] = pa1.y;
            As[(ak4 + 2) * 132 + arow + 64] = pa1.z;
            As[(ak4 + 3) * 132 + arow + 64] = pa1.w;
#pragma unroll
            for (int u = 0; u < 3; ++u)
                if (b_act[u]) {
                    Bs[(b_k4[u] + 0) * 192 + b_slot[u]] = pb[u].x;
                    Bs[(b_k4[u] + 1) * 192 + b_slot[u]] = pb[u].y;
                    Bs[(b_k4[u] + 2) * 192 + b_slot[u]] = pb[u].z;
                    Bs[(b_k4[u] + 3) * 192 + b_slot[u]] = pb[u].w;
                }
            // prefetch next tile (hides LDG under compute)
            if (kt < 15) {
                int ko = (kt + 1) * 16;
                pa0 = *reinterpret_cast<const float4*>(
                    &g_z2[(row0m + arow) * 256 + ko + ak4]);
                pa1 = *reinterpret_cast<const float4*>(
                    &g_z2[(row0m + arow + 64) * 256 + ko + ak4]);
#pragma unroll
                for (int u = 0; u < 3; ++u)
                    if (b_act[u])
                        pb[u] = *reinterpret_cast<const float4*>(
                            &vW3[(size_t)(n0 + b_c[u]) * 256 + ko + b_k4[u]]);
            }
            __syncthreads();   // tile ready

#pragma unroll 4
            for (int k = 0; k < 16; ++k) {
                float4 a0 = *reinterpret_cast<const float4*>(&As[k * 132 + ty8]);
                float4 a1 = *reinterpret_cast<const float4*>(&As[k * 132 + ty8 + 4]);
                float4 b0 = *reinterpret_cast<const float4*>(&Bs[k * 192 + tx12]);
                float4 b1 = *reinterpret_cast<const float4*>(&Bs[k * 192 + tx12 + 4]);
                float  b8 = Bs[k * 192 + tx12 + 8];
                float av[8] = {a0.x, a0.y, a0.z, a0.w, a1.x, a1.y, a1.z, a1.w};
                float bv[9] = {b0.x, b0.y, b0.z, b0.w, b1.x, b1.y, b1.z, b1.w, b8};
#pragma unroll
                for (int i = 0; i < 8; ++i)
#pragma unroll
                    for (int j = 0; j < 9; ++j)
                        acc[i][j] = fmaf(av[i], bv[j], acc[i][j]);
            }
        }

        // epilogue: bias + tanh + contract l (9/thread, 4 threads per s)
        const int tx9 = tx * 9;
#pragma unroll
        for (int i = 0; i < 8; ++i) {
            const int rb = ty8 + i;
            float p = 0.f;
#pragma unroll
            for (int j = 0; j < 9; ++j) {
                float v = tanh_f(acc[i][j] + bsh[tx9 + j]);
                p = fmaf(v, lss[rb * 36 + lbase + j], p);
            }
            p += __shfl_xor_sync(0xffffffffu, p, 1);
            p += __shfl_xor_sync(0xffffffffu, p, 2);
            if (owner) {
                int b = row0m + rb;
                float hn = g_h[b * 256 + s_glob] + p;
                g_h[b * 256 + s_glob] = hn;
                g_hidden[(size_t)(t + 1) * (B_ * S_) + b * 256 + s_glob] = hn;
            }
        }
        tgt += NBLK; grid_barrier(tgt);
    }
}

// ---------------------------------------------------------------------------
// Readout: out[b,t,o] = sum_s hidden[t,b,s] * ro_W[o,s] + ro_b[o]
// grid = (513, 2) x 256.
// ---------------------------------------------------------------------------
__global__ void __launch_bounds__(256)
readout_kernel(const float* __restrict__ roW, const float* __restrict__ rob,
               float* __restrict__ out)
{
    __shared__ float ws[10 * 256];
    __shared__ float hsm[128 * 65];

    const int tid   = threadIdx.x;
    const int t     = blockIdx.x;
    const int bbase = blockIdx.y * 128;

#pragma unroll
    for (int u = 0; u < 10; ++u) ws[tid + 256 * u] = roW[tid + 256 * u];

    const int bl = tid >> 1;
    const int ob = (tid & 1) * 5;
    float acc[5] = {0.f, 0.f, 0.f, 0.f, 0.f};

    for (int sc = 0; sc < 4; ++sc) {
        __syncthreads();
#pragma unroll
        for (int u = 0; u < 8; ++u) {
            int e  = tid + 256 * u;
            int rb = e >> 4;
            int k4 = (e & 15) << 2;
            float4 v = *reinterpret_cast<const float4*>(
                &g_hidden[(size_t)t * (B_ * S_) + (bbase + rb) * 256 + sc * 64 + k4]);
            hsm[rb * 65 + k4 + 0] = v.x;
            hsm[rb * 65 + k4 + 1] = v.y;
            hsm[rb * 65 + k4 + 2] = v.z;
            hsm[rb * 65 + k4 + 3] = v.w;
        }
        __syncthreads();
#pragma unroll 8
        for (int s = 0; s < 64; ++s) {
            float a = hsm[bl * 65 + s];
#pragma unroll
            for (int j = 0; j < 5; ++j)
                acc[j] = fmaf(a, ws[(ob + j) * 256 + sc * 64 + s], acc[j]);
        }
    }

    const int b = bbase + bl;
    size_t o = ((size_t)b * (T_ + 1) + t) * OUT_ + ob;
#pragma unroll
    for (int j = 0; j < 5; ++j)
        out[o + j] = acc[j] + __ldg(rob + ob + j);
}

// ---------------------------------------------------------------------------
// Launch: 3 graph nodes total (init, persistent steps, readout).
// ---------------------------------------------------------------------------
extern "C" void kernel_launch(void* const* d_in, const int* in_sizes, int n_in,
                              void* d_out, int out_size)
{
    const float* x0      = (const float*)d_in[0];
    const float* logsigs = (const float*)d_in[1];
    const float* iW1     = (const float*)d_in[2];
    const float* ib1     = (const float*)d_in[3];
    const float* iW2     = (const float*)d_in[4];
    const float* ib2     = (const float*)d_in[5];
    const float* iW3     = (const float*)d_in[6];
    const float* ib3     = (const float*)d_in[7];
    const float* vW1     = (const float*)d_in[8];
    const float* vb1     = (const float*)d_in[9];
    const float* vW2     = (const float*)d_in[10];
    const float* vb2     = (const float*)d_in[11];
    const float* vW3     = (const float*)d_in[12];
    const float* vb3     = (const float*)d_in[13];
    const float* roW     = (const float*)d_in[14];
    const float* rob     = (const float*)d_in[15];
    float* out = (float*)d_out;

    init_kernel<<<64, 256>>>(x0, iW1, ib1, iW2, ib2, iW3, ib3);
    step_kernel<<<NBLK, 256>>>(vW1, vb1, vW2, vb2, vW3, vb3, logsigs);
    readout_kernel<<<dim3(T_ + 1, 2), 256>>>(roW, rob, out);
}